// round 16
// baseline (speedup 1.0000x reference)
#include <cuda_runtime.h>
#include <cuda_bf16.h>
#include <math.h>
#include <stdint.h>

typedef __nv_bfloat16 bf16;
typedef unsigned long long u64;

// ---------------- problem constants ----------------
#define NTOK_TOTAL 129024   // 5376 windows * 24 tokens
#define NWIN       5376
#define HEADS      6

// ---------------- scratch (device globals) ----------------
__device__ float g_x2  [(size_t)NTOK_TOTAL * 192];
__device__ bf16  g_h   [(size_t)NTOK_TOTAL * 192];
__device__ bf16  g_qkv [(size_t)NTOK_TOTAL * 576];   // [win][head][q|k|v][24][32]
__device__ bf16  g_hid [(size_t)NTOK_TOTAL * 768];
__device__ float g_bias6[HEADS * 576];                // bias[h][m][n]
__device__ bf16 g_qkv_wt [576 * 192];
__device__ bf16 g_proj_wt[192 * 192];
__device__ bf16 g_w1t    [768 * 192];
__device__ bf16 g_w2t    [192 * 768];

// ---------------- helpers ----------------
__device__ __forceinline__ size_t token_src_offset(int t) {
    int wi = t / 24, n = t % 24;
    int i3 = n / 12, j3 = (n >> 1) % 6, k3 = n & 1;
    int d0 = wi % 7;  int r = wi / 7;
    int w0 = r % 16;  r /= 16;
    int h0 = r % 24;  int b0 = r / 24;
    return ((((size_t)b0 * 48 + (h0 * 2 + i3)) * 96 + (w0 * 6 + j3)) * 14
            + (d0 * 2 + k3)) * 192;
}
__device__ __forceinline__ float warp_sum(float v) {
#pragma unroll
    for (int o = 16; o; o >>= 1) v += __shfl_xor_sync(0xffffffffu, v, o);
    return v;
}
__device__ __forceinline__ uint32_t smem_u32(const void* p) {
    uint32_t a;
    asm("{ .reg .u64 t; cvta.to.shared.u64 t, %1; cvt.u32.u64 %0, t; }" : "=r"(a) : "l"(p));
    return a;
}
__device__ __forceinline__ void cp16(uint32_t dst, const void* src) {
    asm volatile("cp.async.cg.shared.global [%0], [%1], 16;" :: "r"(dst), "l"(src));
}
#define CP_COMMIT() asm volatile("cp.async.commit_group;" ::: "memory")
#define CP_WAIT(n)  asm volatile("cp.async.wait_group %0;" :: "n"(n) : "memory")

__device__ __forceinline__ void ldsm_x4(uint32_t* r, uint32_t a) {
    asm volatile("ldmatrix.sync.aligned.m8n8.x4.shared.b16 {%0,%1,%2,%3}, [%4];"
                 : "=r"(r[0]), "=r"(r[1]), "=r"(r[2]), "=r"(r[3]) : "r"(a));
}
__device__ __forceinline__ void mma_bf16(float* d, const uint32_t* a,
                                         const uint32_t* b, const float* c) {
    asm volatile(
        "mma.sync.aligned.m16n8k16.row.col.f32.bf16.bf16.f32 "
        "{%0,%1,%2,%3}, {%4,%5,%6,%7}, {%8,%9}, {%10,%11,%12,%13};"
        : "=f"(d[0]), "=f"(d[1]), "=f"(d[2]), "=f"(d[3])
        : "r"(a[0]), "r"(a[1]), "r"(a[2]), "r"(a[3]),
          "r"(b[0]), "r"(b[1]),
          "f"(c[0]), "f"(c[1]), "f"(c[2]), "f"(c[3]));
}
__device__ __forceinline__ float2 bf2f2(uint32_t u) {
    __nv_bfloat162 b = *reinterpret_cast<__nv_bfloat162*>(&u);
    return __bfloat1622float2(b);
}
__device__ __forceinline__ uint32_t f2bf2u(float lo, float hi) {
    __nv_bfloat162 b = __floats2bfloat162_rn(lo, hi);
    return *reinterpret_cast<uint32_t*>(&b);
}
__device__ __forceinline__ u64 pack2(float lo, float hi) {
    u64 r; asm("mov.b64 %0, {%1, %2};" : "=l"(r) : "f"(lo), "f"(hi)); return r;
}
__device__ __forceinline__ void unpack2(u64 v, float& lo, float& hi) {
    asm("mov.b64 {%0, %1}, %2;" : "=f"(lo), "=f"(hi) : "l"(v));
}
__device__ __forceinline__ u64 fma2(u64 a, u64 b, u64 c) {
    u64 d; asm("fma.rn.f32x2 %0, %1, %2, %3;" : "=l"(d) : "l"(a), "l"(b), "l"(c));
    return d;
}

// ============ fused prep: weight transposes + bias + gather/LN1 ============
__global__ __launch_bounds__(256) void prep_kernel(
    const float* __restrict__ qkv_w, const float* __restrict__ proj_w,
    const float* __restrict__ w1, const float* __restrict__ w2,
    const float* __restrict__ bias_table, const int* __restrict__ rel_index,
    const float* __restrict__ x, const float* __restrict__ gam,
    const float* __restrict__ bet)
{
    int bid = blockIdx.x;
    if (bid < 432) {
        __shared__ float t[32][33];
        const float* W; bf16* Wt; int K, N, loc;
        if (bid < 108)      { W = qkv_w;  Wt = g_qkv_wt;  K = 192; N = 576; loc = bid; }
        else if (bid < 144) { W = proj_w; Wt = g_proj_wt; K = 192; N = 192; loc = bid - 108; }
        else if (bid < 288) { W = w1;     Wt = g_w1t;     K = 192; N = 768; loc = bid - 144; }
        else                { W = w2;     Wt = g_w2t;     K = 768; N = 192; loc = bid - 288; }
        int Kt = K / 32;
        int kb = (loc % Kt) * 32, nb = (loc / Kt) * 32;
        int xx = threadIdx.x & 31, yy = threadIdx.x >> 5;
#pragma unroll
        for (int j = 0; j < 32; j += 8) t[yy + j][xx] = W[(size_t)(kb + yy + j) * N + nb + xx];
        __syncthreads();
#pragma unroll
        for (int j = 0; j < 32; j += 8)
            Wt[(size_t)(nb + yy + j) * K + kb + xx] = __float2bfloat16(t[xx][yy + j]);
    } else if (bid < 446) {
        int idx = (bid - 432) * 256 + threadIdx.x;
        if (idx < HEADS * 576) {
            int h = idx / 576, rem = idx - h * 576;
            int m = rem / 24, n = rem - m * 24;
            g_bias6[h * 576 + rem] = bias_table[rel_index[n * 24 + m] * HEADS + h];
        }
    } else {
        int t = (bid - 446) * 8 + (threadIdx.x >> 5);
        int lane = threadIdx.x & 31;
        size_t src = token_src_offset(t);
        float v[6]; float s = 0.f;
#pragma unroll
        for (int q = 0; q < 6; q++) { v[q] = x[src + lane + q * 32]; s += v[q]; }
        float mean = warp_sum(s) * (1.0f / 192.0f);
        float vs = 0.f;
#pragma unroll
        for (int q = 0; q < 6; q++) { float d = v[q] - mean; vs += d * d; }
        float rstd = rsqrtf(warp_sum(vs) * (1.0f / 192.0f) + 1e-5f);
        size_t dst = (size_t)t * 192;
#pragma unroll
        for (int q = 0; q < 6; q++) {
            int c = lane + q * 32;
            g_h[dst + c] = __float2bfloat16((v[q] - mean) * rstd * gam[c] + bet[c]);
        }
    }
}

// unified dynamic smem symbol (one type across ALL kernels)
extern __shared__ char smem_raw[];

// ====== fused attention + proj + residual + LN2 (2 windows / CTA) ==========
// 384 threads (12 warps). smem layout (bytes):
//   [0, 36864)       kv staging (bf16)  -- reused as attn_out (6 chunks x 48 x 40 halves)
//   [36864, 55296)   q staging (bf16, 12 x 768 halves)
//   [55296, 129024)  kv fp32 (12 x 1536 floats)
//   [129024, 221184) proj B (6 chunks x 192 x 40 halves)
#define APL_SMEM 221184
__global__ __launch_bounds__(384, 1) void attn_proj_ln2_kernel(
    const float* __restrict__ proj_bias, const float* __restrict__ x,
    const float* __restrict__ gam, const float* __restrict__ bet)
{
    char* smem = smem_raw;
    bf16*  kvst = (bf16*)smem;
    bf16*  qst  = (bf16*)(smem + 36864);
    float* kvf  = (float*)(smem + 55296);
    bf16*  ao   = (bf16*)smem;            // attn_out, reuses kv staging
    __shared__ float s_sum[48][4];
    __shared__ float s_sq [48][4];

    const int tid  = threadIdx.x;
    const int lane = tid & 31;
    const int w    = tid >> 5;            // warp 0..11
    const uint32_t sbase = smem_u32(smem);

    // ---- stage qkv for 2 windows (12 pairs) ----
    {
        const bf16* qkv0 = g_qkv + (size_t)blockIdx.x * 12 * 2304;
#pragma unroll
        for (int j = 0; j < 9; j++) {
            int i = tid + j * 384;               // 0..3455
            int pair = i / 288, rem = i % 288;
            int which = rem / 96, e8 = (rem % 96) * 8;
            const bf16* src = qkv0 + (size_t)pair * 2304 + which * 768 + e8;
            uint32_t dst;
            if (which == 0)      dst = sbase + 36864 + (uint32_t)(pair * 768 + e8) * 2;
            else if (which == 1) dst = sbase + (uint32_t)(pair * 1536 + e8) * 2;
            else                 dst = sbase + (uint32_t)(pair * 1536 + 768 + e8) * 2;
            cp16(dst, src);
        }
        CP_COMMIT();
    }
    // ---- stage proj weight (6 LDA-40 chunks) ----
    {
#pragma unroll
        for (int j = 0; j < 12; j++) {
            int i = tid + j * 384;               // 0..4607
            int c = i / 768, rem = i % 768;
            int r = rem / 4, sub = rem % 4;
            cp16(sbase + 129024 + (uint32_t)(((c * 192 + r) * 40 + sub * 8) * 2),
                 g_proj_wt + (size_t)r * 192 + c * 32 + sub * 8);
        }
        CP_COMMIT();
    }

    CP_WAIT(1);          // qkv staged
    __syncthreads();

    // ---- convert k,v staging (bf16) -> kvf (fp32) ----
#pragma unroll
    for (int j = 0; j < 6; j++) {
        int idx = tid + j * 384;                 // 0..2303 uint4 chunks
        uint4 u = ((const uint4*)kvst)[idx];
        float2 f0 = bf2f2(u.x), f1 = bf2f2(u.y), f2 = bf2f2(u.z), f3 = bf2f2(u.w);
        float4* dst = (float4*)(kvf + idx * 8);
        dst[0] = make_float4(f0.x, f0.y, f1.x, f1.y);
        dst[1] = make_float4(f2.x, f2.y, f3.x, f3.y);
    }
    __syncthreads();     // kv staging now dead -> attn_out may overwrite

    // ---- attention: warp w handles pair (ww = w/6 window, h = w%6 head) ----
    {
        const int h  = w % 6;
        const int ww = w / 6;
        const float* kb = kvf + w * 1536;
        const float* vb = kb + 768;
        const float* bias = g_bias6 + h * 576;

        if (lane < 24) {
            const float scale = 0.17677669529663687f;
            u64 q2[16];
            const bf16* qp = qst + w * 768 + lane * 32;
#pragma unroll
            for (int d = 0; d < 32; d += 8) {
                uint4 u = *(const uint4*)(qp + d);
                float2 f;
                f = bf2f2(u.x); q2[(d>>1)+0] = pack2(f.x*scale, f.y*scale);
                f = bf2f2(u.y); q2[(d>>1)+1] = pack2(f.x*scale, f.y*scale);
                f = bf2f2(u.z); q2[(d>>1)+2] = pack2(f.x*scale, f.y*scale);
                f = bf2f2(u.w); q2[(d>>1)+3] = pack2(f.x*scale, f.y*scale);
            }
            float p[24];
            float mx = -1e30f;
#pragma unroll 4
            for (int m = 0; m < 24; m++) {
                const u64* k2p = (const u64*)(kb + m * 32);
                u64 acc = pack2(0.f, 0.f);
#pragma unroll
                for (int i = 0; i < 16; i++) acc = fma2(q2[i], k2p[i], acc);
                float ax, ay; unpack2(acc, ax, ay);
                float a = ax + ay + bias[m * 24 + lane];
                p[m] = a;
                mx = fmaxf(mx, a);
            }
            float sm = 0.f;
#pragma unroll
            for (int m = 0; m < 24; m++) { p[m] = __expf(p[m] - mx); sm += p[m]; }
            float inv = 1.0f / sm;

            u64 o2[16];
            const u64 z = pack2(0.f, 0.f);
#pragma unroll
            for (int i = 0; i < 16; i++) o2[i] = z;
#pragma unroll 4
            for (int m = 0; m < 24; m++) {
                u64 pm2 = pack2(p[m], p[m]);
                const u64* v2p = (const u64*)(vb + m * 32);
#pragma unroll
                for (int i = 0; i < 16; i++) o2[i] = fma2(pm2, v2p[i], o2[i]);
            }
            // write attn_out smem: chunk h, row ww*24+lane, LDA=40 halves
            bf16* op = ao + (size_t)(h * 48 + ww * 24 + lane) * 40;
#pragma unroll
            for (int i = 0; i < 16; i += 4) {
                float a0,a1,b0,b1,c0,c1,d0,d1;
                unpack2(o2[i],   a0, a1); unpack2(o2[i+1], b0, b1);
                unpack2(o2[i+2], c0, c1); unpack2(o2[i+3], d0, d1);
                uint4 u;
                u.x = f2bf2u(a0*inv, a1*inv);
                u.y = f2bf2u(b0*inv, b1*inv);
                u.z = f2bf2u(c0*inv, c1*inv);
                u.w = f2bf2u(d0*inv, d1*inv);
                *(uint4*)(op + i * 2) = u;
            }
        }
    }
    CP_WAIT(0);          // proj B staged
    __syncthreads();     // attn_out visible to all warps

    // ---- proj GEMM from smem: C[48,192] = AO[48,192] @ Bt^T ----
    const int wm = w % 3;        // 16-row group
    const int wn = w / 3;        // 48-col group (0..3)
    const int gq = lane >> 2, tg = lane & 3;

    const uint32_t a_rel = sbase + (uint32_t)(((wm * 16 + (lane & 15)) * 40
                                   + (lane >> 4) * 8) * 2);
    uint32_t b_rel[3];
#pragma unroll
    for (int p = 0; p < 3; p++)
        b_rel[p] = sbase + 129024 +
            (uint32_t)(((wn * 48 + p * 16 + (lane & 7) + ((lane >> 4) << 3)) * 40
                        + ((lane >> 3) & 1) * 8) * 2);

    float acc[6][4];
#pragma unroll
    for (int ni = 0; ni < 6; ni++)
#pragma unroll
        for (int j = 0; j < 4; j++) acc[ni][j] = 0.f;

#pragma unroll
    for (int s = 0; s < 6; s++) {
#pragma unroll
        for (int kk = 0; kk < 32; kk += 16) {
            uint32_t afr[4];
            ldsm_x4(afr, a_rel + (uint32_t)((s * 48 * 40 + kk) * 2));
            uint32_t bfr[6][2];
#pragma unroll
            for (int p = 0; p < 3; p++) {
                uint32_t r4[4];
                ldsm_x4(r4, b_rel[p] + (uint32_t)((s * 192 * 40 + kk) * 2));
                bfr[2*p][0] = r4[0]; bfr[2*p][1] = r4[1];
                bfr[2*p+1][0] = r4[2]; bfr[2*p+1][1] = r4[3];
            }
#pragma unroll
            for (int ni = 0; ni < 6; ni++)
                mma_bf16(acc[ni], afr, bfr[ni], acc[ni]);
        }
    }

    // ---- epilogue: bias + residual(from x) + LN2 ----
    const int row0 = blockIdx.x * 48;
#pragma unroll
    for (int hh = 0; hh < 2; hh++) {
        int rl = wm * 16 + gq + hh * 8;
        int r  = row0 + rl;
        size_t roff = token_src_offset(r);
        float s1 = 0.f, s2 = 0.f;
#pragma unroll
        for (int ni = 0; ni < 6; ni++) {
            int col = wn * 48 + ni * 8 + tg * 2;
            float2 rx = *(const float2*)(x + roff + col);
            float v0 = acc[ni][hh*2]     + proj_bias[col]     + rx.x;
            float v1 = acc[ni][hh*2 + 1] + proj_bias[col + 1] + rx.y;
            acc[ni][hh*2]     = v0;
            acc[ni][hh*2 + 1] = v1;
            s1 += v0 + v1;
            s2 += v0 * v0 + v1 * v1;
        }
        s1 += __shfl_xor_sync(0xffffffffu, s1, 1);
        s1 += __shfl_xor_sync(0xffffffffu, s1, 2);
        s2 += __shfl_xor_sync(0xffffffffu, s2, 1);
        s2 += __shfl_xor_sync(0xffffffffu, s2, 2);
        if (tg == 0) { s_sum[rl][wn] = s1; s_sq[rl][wn] = s2; }
    }
    __syncthreads();
#pragma unroll
    for (int hh = 0; hh < 2; hh++) {
        int rl = wm * 16 + gq + hh * 8;
        int r  = row0 + rl;
        float S1 = s_sum[rl][0] + s_sum[rl][1] + s_sum[rl][2] + s_sum[rl][3];
        float S2 = s_sq [rl][0] + s_sq [rl][1] + s_sq [rl][2] + s_sq [rl][3];
        float mean = S1 * (1.0f / 192.0f);
        float var  = S2 * (1.0f / 192.0f) - mean * mean;
        float rstd = rsqrtf(var + 1e-5f);
#pragma unroll
        for (int ni = 0; ni < 6; ni++) {
            int col = wn * 48 + ni * 8 + tg * 2;
            float v0 = acc[ni][hh*2], v1 = acc[ni][hh*2 + 1];
            *(float2*)(g_x2 + (size_t)r * 192 + col) = make_float2(v0, v1);
            float n0 = (v0 - mean) * rstd * gam[col]     + bet[col];
            float n1 = (v1 - mean) * rstd * gam[col + 1] + bet[col + 1];
            *(__nv_bfloat162*)(g_h + (size_t)r * 192 + col) =
                __floats2bfloat162_rn(n0, n1);
        }
    }
}

// ======================= generic bf16 GEMM (BN=96) ==========================
#define GEMM_SMEM (3 * (128 + 96) * 40 * 2)
template <int EPI>
__global__ __launch_bounds__(256, 3) void tc_gemm(
    const bf16* __restrict__ A, const bf16* __restrict__ Bt,
    const float* __restrict__ bias, const float* __restrict__ res,
    void* __restrict__ Cc, int N, int K)
{
    constexpr int LDA = 40;
    constexpr int ASZ = 128 * LDA, BSZ = 96 * LDA;
    bf16* smem = (bf16*)smem_raw;
    bf16* Asb = smem;
    bf16* Bsb = smem + 3 * ASZ;

    const int tid  = threadIdx.x;
    const int lane = tid & 31;
    const int wid  = tid >> 5;
    const int wm   = wid & 3;
    const int wn   = wid >> 2;
    const int col0 = blockIdx.x * 96;
    const int row0 = blockIdx.y * 128;
    const int gq = lane >> 2, tg = lane & 3;

    const uint32_t sAb = smem_u32(Asb), sBb = smem_u32(Bsb);
    const uint32_t a_rel = (uint32_t)(((wm * 32 + (lane & 15)) * LDA
                                       + (lane >> 4) * 8) * 2);
    uint32_t b_rel[3];
#pragma unroll
    for (int p = 0; p < 3; p++)
        b_rel[p] = (uint32_t)(((wn * 48 + p * 16 + (lane & 7) + ((lane >> 4) << 3)) * LDA
                              + ((lane >> 3) & 1) * 8) * 2);
    const int cr0 = tid >> 2, cr1 = (tid + 256) >> 2, cc = (tid & 3);
    const uint32_t cpa0 = (uint32_t)(cr0 * 80 + cc * 16);
    const uint32_t cpa1 = (uint32_t)(cr1 * 80 + cc * 16);

    float acc[2][6][4];
#pragma unroll
    for (int mi = 0; mi < 2; mi++)
#pragma unroll
        for (int ni = 0; ni < 6; ni++)
#pragma unroll
            for (int j = 0; j < 4; j++) acc[mi][ni][j] = 0.f;

    const int nstages = K / 32;

    auto prefetch = [&](int s, int b) {
        const bf16* Ag = A + (size_t)row0 * K + s * 32 + cc * 8;
        const bf16* Bg = Bt + (size_t)col0 * K + s * 32 + cc * 8;
        uint32_t sA = sAb + (uint32_t)b * (ASZ * 2);
        uint32_t sB = sBb + (uint32_t)b * (BSZ * 2);
        cp16(sA + cpa0, Ag + (size_t)cr0 * K);
        cp16(sA + cpa1, Ag + (size_t)cr1 * K);
        cp16(sB + cpa0, Bg + (size_t)cr0 * K);
        if (tid < 128)
            cp16(sB + cpa1, Bg + (size_t)cr1 * K);
        CP_COMMIT();
    };

    prefetch(0, 0);
    prefetch(1, 1);

    for (int s = 0; s < nstages; s++) {
        if (s < nstages - 1) CP_WAIT(1); else CP_WAIT(0);
        __syncthreads();
        if (s + 2 < nstages) prefetch(s + 2, (s + 2) % 3);

        const int b = s % 3;
        const uint32_t sA = sAb + (uint32_t)b * (ASZ * 2) + a_rel;
        const uint32_t sBB = sBb + (uint32_t)b * (BSZ * 2);
#pragma unroll
        for (int kk = 0; kk < 32; kk += 16) {
            uint32_t afr[2][4];
#pragma unroll
            for (int mi = 0; mi < 2; mi++)
                ldsm_x4(afr[mi], sA + (uint32_t)(kk * 2 + mi * (16 * LDA * 2)));

            uint32_t bfr[6][2];
#pragma unroll
            for (int p = 0; p < 3; p++) {
                uint32_t r4[4];
                ldsm_x4(r4, sBB + b_rel[p] + (uint32_t)(kk * 2));
                bfr[2*p][0] = r4[0]; bfr[2*p][1] = r4[1];
                bfr[2*p+1][0] = r4[2]; bfr[2*p+1][1] = r4[3];
            }
#pragma unroll
            for (int mi = 0; mi < 2; mi++)
#pragma unroll
                for (int ni = 0; ni < 6; ni++)
                    mma_bf16(acc[mi][ni], afr[mi], bfr[ni], acc[mi][ni]);
        }
    }

#pragma unroll
    for (int mi = 0; mi < 2; mi++) {
#pragma unroll
        for (int ni = 0; ni < 6; ni++) {
            int row = row0 + wm * 32 + mi * 16 + gq;
            int col = col0 + wn * 48 + ni * 8 + tg * 2;
            float b0 = bias[col], b1 = bias[col + 1];
#pragma unroll
            for (int hh = 0; hh < 2; hh++) {
                int r = row + hh * 8;
                float v0 = acc[mi][ni][hh * 2]     + b0;
                float v1 = acc[mi][ni][hh * 2 + 1] + b1;
                if (EPI == 1) {
                    v0 = 0.5f * v0 * (1.0f + erff(v0 * 0.70710678118654752f));
                    v1 = 0.5f * v1 * (1.0f + erff(v1 * 0.70710678118654752f));
                }
                if (EPI == 0) {
                    int wi2 = r / 24, n2 = r - wi2 * 24;
                    int which = col / 192;
                    int rem = col - which * 192;
                    int h2 = rem >> 5, d2 = rem & 31;
                    bf16* cp_ = (bf16*)Cc +
                        ((((size_t)wi2 * 6 + h2) * 3 + which) * 768 + n2 * 32 + d2);
                    *(__nv_bfloat162*)cp_ = __floats2bfloat162_rn(v0, v1);
                } else if (EPI == 3) {
                    const float* rp = res + (size_t)r * 192 + col;
                    v0 += rp[0]; v1 += rp[1];
                    size_t off = token_src_offset(r) + col;
                    *(float2*)((float*)Cc + off) = make_float2(v0, v1);
                } else {
                    bf16* cp_ = (bf16*)Cc + (size_t)r * N + col;
                    *(__nv_bfloat162*)cp_ = __floats2bfloat162_rn(v0, v1);
                }
            }
        }
    }
}

// ---------------- host launcher ----------------
extern "C" void kernel_launch(void* const* d_in, const int* in_sizes, int n_in,
                              void* d_out, int out_size)
{
    const float* x      = (const float*)d_in[0];
    const float* ln1_g  = (const float*)d_in[1];
    const float* ln1_b  = (const float*)d_in[2];
    const float* qkv_w  = (const float*)d_in[3];
    const float* qkv_b  = (const float*)d_in[4];
    const float* btab   = (const float*)d_in[5];
    const float* proj_w = (const float*)d_in[6];
    const float* proj_b = (const float*)d_in[7];
    const float* ln2_g  = (const float*)d_in[8];
    const float* ln2_b  = (const float*)d_in[9];
    const float* mlp_w1 = (const float*)d_in[10];
    const float* mlp_b1 = (const float*)d_in[11];
    const float* mlp_w2 = (const float*)d_in[12];
    const float* mlp_b2 = (const float*)d_in[13];
    const int*   rel_idx= (const int*)d_in[14];
    float*       out    = (float*)d_out;

    bf16 *p_h, *p_qkv, *p_hid;
    float *p_x2;
    bf16 *p_qkv_wt, *p_w1t, *p_w2t;
    cudaGetSymbolAddress((void**)&p_h,    g_h);
    cudaGetSymbolAddress((void**)&p_qkv,  g_qkv);
    cudaGetSymbolAddress((void**)&p_x2,   g_x2);
    cudaGetSymbolAddress((void**)&p_hid,  g_hid);
    cudaGetSymbolAddress((void**)&p_qkv_wt,  g_qkv_wt);
    cudaGetSymbolAddress((void**)&p_w1t,  g_w1t);
    cudaGetSymbolAddress((void**)&p_w2t,  g_w2t);

    cudaFuncSetAttribute(tc_gemm<0>, cudaFuncAttributeMaxDynamicSharedMemorySize, GEMM_SMEM);
    cudaFuncSetAttribute(tc_gemm<1>, cudaFuncAttributeMaxDynamicSharedMemorySize, GEMM_SMEM);
    cudaFuncSetAttribute(tc_gemm<3>, cudaFuncAttributeMaxDynamicSharedMemorySize, GEMM_SMEM);
    cudaFuncSetAttribute(attn_proj_ln2_kernel, cudaFuncAttributeMaxDynamicSharedMemorySize, APL_SMEM);

    prep_kernel<<<446 + NTOK_TOTAL / 8, 256>>>(qkv_w, proj_w, mlp_w1, mlp_w2,
                                               btab, rel_idx, x, ln1_g, ln1_b);

    const int Mb = NTOK_TOTAL / 128;  // 1008
    tc_gemm<0><<<dim3(6, Mb), 256, GEMM_SMEM>>>(p_h, p_qkv_wt, qkv_b, nullptr, p_qkv, 576, 192);
    // fused attention + proj + residual + LN2
    attn_proj_ln2_kernel<<<NWIN / 2, 384, APL_SMEM>>>(proj_b, x, ln2_g, ln2_b);
    tc_gemm<1><<<dim3(8, Mb), 256, GEMM_SMEM>>>(p_h, p_w1t, mlp_b1, nullptr, p_hid, 768, 192);
    tc_gemm<3><<<dim3(2, Mb), 256, GEMM_SMEM>>>(p_hid, p_w2t, mlp_b2, p_x2, out, 192, 768);
}

// round 17
// speedup vs baseline: 1.1090x; 1.1090x over previous
#include <cuda_runtime.h>
#include <cuda_bf16.h>
#include <math.h>
#include <stdint.h>

typedef __nv_bfloat16 bf16;
typedef unsigned long long u64;

// ---------------- problem constants ----------------
#define NTOK_TOTAL 129024   // 5376 windows * 24 tokens
#define NWIN       5376
#define HEADS      6

// ---------------- scratch (device globals) ----------------
__device__ float g_x2  [(size_t)NTOK_TOTAL * 192];
__device__ bf16  g_h   [(size_t)NTOK_TOTAL * 192];
__device__ bf16  g_qkv [(size_t)NTOK_TOTAL * 576];   // [win][head][q|k|v][24][32]
__device__ bf16  g_attn[(size_t)NTOK_TOTAL * 192];   // [win][head][24][32]
__device__ bf16  g_hid [(size_t)NTOK_TOTAL * 768];
__device__ float g_bias6[HEADS * 576];                // bias[h][m][n]
__device__ bf16 g_qkv_wt [576 * 192];
__device__ bf16 g_proj_wt[192 * 192];
__device__ bf16 g_w1t    [768 * 192];
__device__ bf16 g_w2t    [192 * 768];

// ---------------- helpers ----------------
__device__ __forceinline__ size_t token_src_offset(int t) {
    int wi = t / 24, n = t % 24;
    int i3 = n / 12, j3 = (n >> 1) % 6, k3 = n & 1;
    int d0 = wi % 7;  int r = wi / 7;
    int w0 = r % 16;  r /= 16;
    int h0 = r % 24;  int b0 = r / 24;
    return ((((size_t)b0 * 48 + (h0 * 2 + i3)) * 96 + (w0 * 6 + j3)) * 14
            + (d0 * 2 + k3)) * 192;
}
__device__ __forceinline__ float warp_sum(float v) {
#pragma unroll
    for (int o = 16; o; o >>= 1) v += __shfl_xor_sync(0xffffffffu, v, o);
    return v;
}
__device__ __forceinline__ uint32_t smem_u32(const void* p) {
    uint32_t a;
    asm("{ .reg .u64 t; cvta.to.shared.u64 t, %1; cvt.u32.u64 %0, t; }" : "=r"(a) : "l"(p));
    return a;
}
__device__ __forceinline__ void cp16(uint32_t dst, const void* src) {
    asm volatile("cp.async.cg.shared.global [%0], [%1], 16;" :: "r"(dst), "l"(src));
}
#define CP_COMMIT() asm volatile("cp.async.commit_group;" ::: "memory")
#define CP_WAIT(n)  asm volatile("cp.async.wait_group %0;" :: "n"(n) : "memory")

__device__ __forceinline__ void ldsm_x4(uint32_t* r, uint32_t a) {
    asm volatile("ldmatrix.sync.aligned.m8n8.x4.shared.b16 {%0,%1,%2,%3}, [%4];"
                 : "=r"(r[0]), "=r"(r[1]), "=r"(r[2]), "=r"(r[3]) : "r"(a));
}
__device__ __forceinline__ void mma_bf16(float* d, const uint32_t* a,
                                         const uint32_t* b, const float* c) {
    asm volatile(
        "mma.sync.aligned.m16n8k16.row.col.f32.bf16.bf16.f32 "
        "{%0,%1,%2,%3}, {%4,%5,%6,%7}, {%8,%9}, {%10,%11,%12,%13};"
        : "=f"(d[0]), "=f"(d[1]), "=f"(d[2]), "=f"(d[3])
        : "r"(a[0]), "r"(a[1]), "r"(a[2]), "r"(a[3]),
          "r"(b[0]), "r"(b[1]),
          "f"(c[0]), "f"(c[1]), "f"(c[2]), "f"(c[3]));
}
__device__ __forceinline__ float2 bf2f2(uint32_t u) {
    __nv_bfloat162 b = *reinterpret_cast<__nv_bfloat162*>(&u);
    return __bfloat1622float2(b);
}
__device__ __forceinline__ uint32_t f2bf2u(float lo, float hi) {
    __nv_bfloat162 b = __floats2bfloat162_rn(lo, hi);
    return *reinterpret_cast<uint32_t*>(&b);
}
__device__ __forceinline__ u64 pack2(float lo, float hi) {
    u64 r; asm("mov.b64 %0, {%1, %2};" : "=l"(r) : "f"(lo), "f"(hi)); return r;
}
__device__ __forceinline__ void unpack2(u64 v, float& lo, float& hi) {
    asm("mov.b64 {%0, %1}, %2;" : "=f"(lo), "=f"(hi) : "l"(v));
}
__device__ __forceinline__ u64 fma2(u64 a, u64 b, u64 c) {
    u64 d; asm("fma.rn.f32x2 %0, %1, %2, %3;" : "=l"(d) : "l"(a), "l"(b), "l"(c));
    return d;
}
// fast GELU via hw tanh (error << bf16 quantization of the hidden buffer)
__device__ __forceinline__ float gelu_fast(float v) {
    float t;
    float s = 0.7978845608028654f * (v + 0.044715f * v * v * v);
    asm("tanh.approx.f32 %0, %1;" : "=f"(t) : "f"(s));
    return 0.5f * v * (1.0f + t);
}

// ============ fused prep: weight transposes + bias + gather/LN1 ============
__global__ __launch_bounds__(256) void prep_kernel(
    const float* __restrict__ qkv_w, const float* __restrict__ proj_w,
    const float* __restrict__ w1, const float* __restrict__ w2,
    const float* __restrict__ bias_table, const int* __restrict__ rel_index,
    const float* __restrict__ x, const float* __restrict__ gam,
    const float* __restrict__ bet)
{
    int bid = blockIdx.x;
    if (bid < 432) {
        __shared__ float t[32][33];
        const float* W; bf16* Wt; int K, N, loc;
        if (bid < 108)      { W = qkv_w;  Wt = g_qkv_wt;  K = 192; N = 576; loc = bid; }
        else if (bid < 144) { W = proj_w; Wt = g_proj_wt; K = 192; N = 192; loc = bid - 108; }
        else if (bid < 288) { W = w1;     Wt = g_w1t;     K = 192; N = 768; loc = bid - 144; }
        else                { W = w2;     Wt = g_w2t;     K = 768; N = 192; loc = bid - 288; }
        int Kt = K / 32;
        int kb = (loc % Kt) * 32, nb = (loc / Kt) * 32;
        int xx = threadIdx.x & 31, yy = threadIdx.x >> 5;
#pragma unroll
        for (int j = 0; j < 32; j += 8) t[yy + j][xx] = W[(size_t)(kb + yy + j) * N + nb + xx];
        __syncthreads();
#pragma unroll
        for (int j = 0; j < 32; j += 8)
            Wt[(size_t)(nb + yy + j) * K + kb + xx] = __float2bfloat16(t[xx][yy + j]);
    } else if (bid < 446) {
        int idx = (bid - 432) * 256 + threadIdx.x;
        if (idx < HEADS * 576) {
            int h = idx / 576, rem = idx - h * 576;
            int m = rem / 24, n = rem - m * 24;
            g_bias6[h * 576 + rem] = bias_table[rel_index[n * 24 + m] * HEADS + h];
        }
    } else {
        int t = (bid - 446) * 8 + (threadIdx.x >> 5);
        int lane = threadIdx.x & 31;
        size_t src = token_src_offset(t);
        float v[6]; float s = 0.f;
#pragma unroll
        for (int q = 0; q < 6; q++) { v[q] = x[src + lane + q * 32]; s += v[q]; }
        float mean = warp_sum(s) * (1.0f / 192.0f);
        float vs = 0.f;
#pragma unroll
        for (int q = 0; q < 6; q++) { float d = v[q] - mean; vs += d * d; }
        float rstd = rsqrtf(warp_sum(vs) * (1.0f / 192.0f) + 1e-5f);
        size_t dst = (size_t)t * 192;
#pragma unroll
        for (int q = 0; q < 6; q++) {
            int c = lane + q * 32;
            g_h[dst + c] = __float2bfloat16((v[q] - mean) * rstd * gam[c] + bet[c]);
        }
    }
}

// ---------------- attention: packed f32x2 math, shfl-free softmax -----------
__global__ __launch_bounds__(256) void attn_kernel()
{
    __shared__ __align__(16) float k_s[8][768];
    __shared__ __align__(16) float v_s[8][768];
    const int w = threadIdx.x >> 5, lane = threadIdx.x & 31;
    const int pair = blockIdx.x * 8 + w;
    const int h = pair % 6;
    const bf16* base = g_qkv + (size_t)pair * 2304;
    const float* bias = g_bias6 + h * 576;

#pragma unroll
    for (int j = 0; j < 3; j++) {
        int idx = (lane + j * 32) * 8;
        uint4 uk = *(const uint4*)(base + 768 + idx);
        uint4 uv = *(const uint4*)(base + 1536 + idx);
        float2 f;
        f = bf2f2(uk.x); k_s[w][idx+0] = f.x; k_s[w][idx+1] = f.y;
        f = bf2f2(uk.y); k_s[w][idx+2] = f.x; k_s[w][idx+3] = f.y;
        f = bf2f2(uk.z); k_s[w][idx+4] = f.x; k_s[w][idx+5] = f.y;
        f = bf2f2(uk.w); k_s[w][idx+6] = f.x; k_s[w][idx+7] = f.y;
        f = bf2f2(uv.x); v_s[w][idx+0] = f.x; v_s[w][idx+1] = f.y;
        f = bf2f2(uv.y); v_s[w][idx+2] = f.x; v_s[w][idx+3] = f.y;
        f = bf2f2(uv.z); v_s[w][idx+4] = f.x; v_s[w][idx+5] = f.y;
        f = bf2f2(uv.w); v_s[w][idx+6] = f.x; v_s[w][idx+7] = f.y;
    }
    __syncwarp();

    if (lane < 24) {
        const float scale = 0.17677669529663687f;
        u64 q2[16];
        const bf16* qp = base + lane * 32;
#pragma unroll
        for (int d = 0; d < 32; d += 8) {
            uint4 u = *(const uint4*)(qp + d);
            float2 f;
            f = bf2f2(u.x); q2[(d>>1)+0] = pack2(f.x*scale, f.y*scale);
            f = bf2f2(u.y); q2[(d>>1)+1] = pack2(f.x*scale, f.y*scale);
            f = bf2f2(u.z); q2[(d>>1)+2] = pack2(f.x*scale, f.y*scale);
            f = bf2f2(u.w); q2[(d>>1)+3] = pack2(f.x*scale, f.y*scale);
        }
        float p[24];
        float mx = -1e30f;
#pragma unroll 4
        for (int m = 0; m < 24; m++) {
            const u64* k2p = (const u64*)&k_s[w][m * 32];
            u64 acc = pack2(0.f, 0.f);
#pragma unroll
            for (int i = 0; i < 16; i++) acc = fma2(q2[i], k2p[i], acc);
            float ax, ay; unpack2(acc, ax, ay);
            float a = ax + ay + bias[m * 24 + lane];
            p[m] = a;
            mx = fmaxf(mx, a);
        }
        float sm = 0.f;
#pragma unroll
        for (int m = 0; m < 24; m++) { p[m] = __expf(p[m] - mx); sm += p[m]; }
        float inv = 1.0f / sm;

        u64 o2[16];
        const u64 z = pack2(0.f, 0.f);
#pragma unroll
        for (int i = 0; i < 16; i++) o2[i] = z;
#pragma unroll 4
        for (int m = 0; m < 24; m++) {
            u64 pm2 = pack2(p[m], p[m]);
            const u64* v2p = (const u64*)&v_s[w][m * 32];
#pragma unroll
            for (int i = 0; i < 16; i++) o2[i] = fma2(pm2, v2p[i], o2[i]);
        }
        bf16* ob = g_attn + (size_t)pair * 768 + lane * 32;
#pragma unroll
        for (int i = 0; i < 16; i += 4) {
            float a0,a1,b0,b1,c0,c1,d0,d1;
            unpack2(o2[i],   a0, a1); unpack2(o2[i+1], b0, b1);
            unpack2(o2[i+2], c0, c1); unpack2(o2[i+3], d0, d1);
            uint4 u;
            u.x = f2bf2u(a0*inv, a1*inv);
            u.y = f2bf2u(b0*inv, b1*inv);
            u.z = f2bf2u(c0*inv, c1*inv);
            u.w = f2bf2u(d0*inv, d1*inv);
            *(uint4*)(ob + i * 2) = u;
        }
    }
}

// unified dynamic smem symbol
extern __shared__ char smem_raw[];

// ======================= generic bf16 GEMM (BN=96) ==========================
#define GEMM_SMEM (3 * (128 + 96) * 40 * 2)
template <int EPI>
__global__ __launch_bounds__(256, 3) void tc_gemm(
    const bf16* __restrict__ A, const bf16* __restrict__ Bt,
    const float* __restrict__ bias, const float* __restrict__ res,
    void* __restrict__ Cc, int N, int K)
{
    constexpr int LDA = 40;
    constexpr int ASZ = 128 * LDA, BSZ = 96 * LDA;
    bf16* smem = (bf16*)smem_raw;
    bf16* Asb = smem;
    bf16* Bsb = smem + 3 * ASZ;

    const int tid  = threadIdx.x;
    const int lane = tid & 31;
    const int wid  = tid >> 5;
    const int wm   = wid & 3;
    const int wn   = wid >> 2;
    const int col0 = blockIdx.x * 96;
    const int row0 = blockIdx.y * 128;
    const int gq = lane >> 2, tg = lane & 3;

    const uint32_t sAb = smem_u32(Asb), sBb = smem_u32(Bsb);
    const uint32_t a_rel = (uint32_t)(((wm * 32 + (lane & 15)) * LDA
                                       + (lane >> 4) * 8) * 2);
    uint32_t b_rel[3];
#pragma unroll
    for (int p = 0; p < 3; p++)
        b_rel[p] = (uint32_t)(((wn * 48 + p * 16 + (lane & 7) + ((lane >> 4) << 3)) * LDA
                              + ((lane >> 3) & 1) * 8) * 2);
    const int cr0 = tid >> 2, cr1 = (tid + 256) >> 2, cc = (tid & 3);
    const uint32_t cpa0 = (uint32_t)(cr0 * 80 + cc * 16);
    const uint32_t cpa1 = (uint32_t)(cr1 * 80 + cc * 16);

    float acc[2][6][4];
#pragma unroll
    for (int mi = 0; mi < 2; mi++)
#pragma unroll
        for (int ni = 0; ni < 6; ni++)
#pragma unroll
            for (int j = 0; j < 4; j++) acc[mi][ni][j] = 0.f;

    const int nstages = K / 32;

    auto prefetch = [&](int s, int b) {
        const bf16* Ag = A + (size_t)row0 * K + s * 32 + cc * 8;
        const bf16* Bg = Bt + (size_t)col0 * K + s * 32 + cc * 8;
        uint32_t sA = sAb + (uint32_t)b * (ASZ * 2);
        uint32_t sB = sBb + (uint32_t)b * (BSZ * 2);
        cp16(sA + cpa0, Ag + (size_t)cr0 * K);
        cp16(sA + cpa1, Ag + (size_t)cr1 * K);
        cp16(sB + cpa0, Bg + (size_t)cr0 * K);
        if (tid < 128)
            cp16(sB + cpa1, Bg + (size_t)cr1 * K);
        CP_COMMIT();
    };

    prefetch(0, 0);
    prefetch(1, 1);

    for (int s = 0; s < nstages; s++) {
        if (s < nstages - 1) CP_WAIT(1); else CP_WAIT(0);
        __syncthreads();
        if (s + 2 < nstages) prefetch(s + 2, (s + 2) % 3);

        const int b = s % 3;
        const uint32_t sA = sAb + (uint32_t)b * (ASZ * 2) + a_rel;
        const uint32_t sBB = sBb + (uint32_t)b * (BSZ * 2);
#pragma unroll
        for (int kk = 0; kk < 32; kk += 16) {
            uint32_t afr[2][4];
#pragma unroll
            for (int mi = 0; mi < 2; mi++)
                ldsm_x4(afr[mi], sA + (uint32_t)(kk * 2 + mi * (16 * LDA * 2)));

            uint32_t bfr[6][2];
#pragma unroll
            for (int p = 0; p < 3; p++) {
                uint32_t r4[4];
                ldsm_x4(r4, sBB + b_rel[p] + (uint32_t)(kk * 2));
                bfr[2*p][0] = r4[0]; bfr[2*p][1] = r4[1];
                bfr[2*p+1][0] = r4[2]; bfr[2*p+1][1] = r4[3];
            }
#pragma unroll
            for (int mi = 0; mi < 2; mi++)
#pragma unroll
                for (int ni = 0; ni < 6; ni++)
                    mma_bf16(acc[mi][ni], afr[mi], bfr[ni], acc[mi][ni]);
        }
    }

#pragma unroll
    for (int mi = 0; mi < 2; mi++) {
#pragma unroll
        for (int ni = 0; ni < 6; ni++) {
            int row = row0 + wm * 32 + mi * 16 + gq;
            int col = col0 + wn * 48 + ni * 8 + tg * 2;
            float b0 = bias[col], b1 = bias[col + 1];
#pragma unroll
            for (int hh = 0; hh < 2; hh++) {
                int r = row + hh * 8;
                float v0 = acc[mi][ni][hh * 2]     + b0;
                float v1 = acc[mi][ni][hh * 2 + 1] + b1;
                if (EPI == 1) {
                    v0 = gelu_fast(v0);
                    v1 = gelu_fast(v1);
                }
                if (EPI == 0) {
                    int wi2 = r / 24, n2 = r - wi2 * 24;
                    int which = col / 192;
                    int rem = col - which * 192;
                    int h2 = rem >> 5, d2 = rem & 31;
                    bf16* cp_ = (bf16*)Cc +
                        ((((size_t)wi2 * 6 + h2) * 3 + which) * 768 + n2 * 32 + d2);
                    *(__nv_bfloat162*)cp_ = __floats2bfloat162_rn(v0, v1);
                } else if (EPI == 3) {
                    const float* rp = res + (size_t)r * 192 + col;
                    v0 += rp[0]; v1 += rp[1];
                    size_t off = token_src_offset(r) + col;
                    *(float2*)((float*)Cc + off) = make_float2(v0, v1);
                } else {
                    bf16* cp_ = (bf16*)Cc + (size_t)r * N + col;
                    *(__nv_bfloat162*)cp_ = __floats2bfloat162_rn(v0, v1);
                }
            }
        }
    }
}

// ===== proj GEMM (BM=64, BN=192) + residual(from x) + LN2, 3 CTAs/SM ========
#define PROJ_SMEM (3 * (64 + 192) * 40 * 2)
__global__ __launch_bounds__(256, 3) void proj_ln2_kernel(
    const bf16* __restrict__ A, const bf16* __restrict__ Bt,
    const float* __restrict__ bias, const float* __restrict__ x,
    const float* __restrict__ gam, const float* __restrict__ bet)
{
    constexpr int LDA = 40, K = 192;
    constexpr int ASZ = 64 * LDA, BSZ = 192 * LDA;
    bf16* smem = (bf16*)smem_raw;
    bf16* Asb = smem;
    bf16* Bsb = smem + 3 * ASZ;
    __shared__ float s_sum[64][4];
    __shared__ float s_sq [64][4];

    const int tid  = threadIdx.x;
    const int lane = tid & 31;
    const int wid  = tid >> 5;
    const int wm   = wid & 1;
    const int wn   = wid >> 1;
    const int row0 = blockIdx.x * 64;
    const int gq = lane >> 2, tg = lane & 3;

    const uint32_t sAb = smem_u32(Asb), sBb = smem_u32(Bsb);
    const uint32_t a_rel = (uint32_t)(((wm * 32 + (lane & 15)) * LDA
                                       + (lane >> 4) * 8) * 2);
    uint32_t b_rel[3];
#pragma unroll
    for (int p = 0; p < 3; p++)
        b_rel[p] = (uint32_t)(((wn * 48 + p * 16 + (lane & 7) + ((lane >> 4) << 3)) * LDA
                              + ((lane >> 3) & 1) * 8) * 2);

    float acc[2][6][4];
#pragma unroll
    for (int mi = 0; mi < 2; mi++)
#pragma unroll
        for (int ni = 0; ni < 6; ni++)
#pragma unroll
            for (int j = 0; j < 4; j++) acc[mi][ni][j] = 0.f;

    const int nstages = 6;

    auto prefetch = [&](int s, int b) {
        const bf16* Bg = Bt + (size_t)s * 32;
        uint32_t sA = sAb + (uint32_t)b * (ASZ * 2);
        uint32_t sB = sBb + (uint32_t)b * (BSZ * 2);
        {
            int r = tid >> 2, c4 = tid & 3;
            int rg = row0 + r;
            int win = rg / 24, n2 = rg - win * 24;
            const bf16* src = A + ((size_t)win * 6 + s) * 768 + n2 * 32 + c4 * 8;
            cp16(sA + (uint32_t)(r * 80 + c4 * 16), src);
        }
#pragma unroll
        for (int j = 0; j < 3; j++) {
            int idx = tid + j * 256;
            int r = idx >> 2, c = idx & 3;
            cp16(sB + (uint32_t)(r * 80 + c * 16), Bg + (size_t)r * K + c * 8);
        }
        CP_COMMIT();
    };

    prefetch(0, 0);
    prefetch(1, 1);

    for (int s = 0; s < nstages; s++) {
        if (s < nstages - 1) CP_WAIT(1); else CP_WAIT(0);
        __syncthreads();
        if (s + 2 < nstages) prefetch(s + 2, (s + 2) % 3);

        const int b = s % 3;
        const uint32_t sA = sAb + (uint32_t)b * (ASZ * 2) + a_rel;
        const uint32_t sBB = sBb + (uint32_t)b * (BSZ * 2);
#pragma unroll
        for (int kk = 0; kk < 32; kk += 16) {
            uint32_t afr[2][4];
#pragma unroll
            for (int mi = 0; mi < 2; mi++)
                ldsm_x4(afr[mi], sA + (uint32_t)(kk * 2 + mi * (16 * LDA * 2)));

            uint32_t bfr[6][2];
#pragma unroll
            for (int p = 0; p < 3; p++) {
                uint32_t r4[4];
                ldsm_x4(r4, sBB + b_rel[p] + (uint32_t)(kk * 2));
                bfr[2*p][0] = r4[0]; bfr[2*p][1] = r4[1];
                bfr[2*p+1][0] = r4[2]; bfr[2*p+1][1] = r4[3];
            }
#pragma unroll
            for (int mi = 0; mi < 2; mi++)
#pragma unroll
                for (int ni = 0; ni < 6; ni++)
                    mma_bf16(acc[mi][ni], afr[mi], bfr[ni], acc[mi][ni]);
        }
    }

#pragma unroll
    for (int mi = 0; mi < 2; mi++) {
#pragma unroll
        for (int hh = 0; hh < 2; hh++) {
            int rl = wm * 32 + mi * 16 + gq + hh * 8;
            int r  = row0 + rl;
            size_t roff = token_src_offset(r);
            float s1 = 0.f, s2 = 0.f;
#pragma unroll
            for (int ni = 0; ni < 6; ni++) {
                int col = wn * 48 + ni * 8 + tg * 2;
                float2 rx = *(const float2*)(x + roff + col);
                float v0 = acc[mi][ni][hh*2]     + bias[col]     + rx.x;
                float v1 = acc[mi][ni][hh*2 + 1] + bias[col + 1] + rx.y;
                acc[mi][ni][hh*2]     = v0;
                acc[mi][ni][hh*2 + 1] = v1;
                s1 += v0 + v1;
                s2 += v0 * v0 + v1 * v1;
            }
            s1 += __shfl_xor_sync(0xffffffffu, s1, 1);
            s1 += __shfl_xor_sync(0xffffffffu, s1, 2);
            s2 += __shfl_xor_sync(0xffffffffu, s2, 1);
            s2 += __shfl_xor_sync(0xffffffffu, s2, 2);
            if (tg == 0) { s_sum[rl][wn] = s1; s_sq[rl][wn] = s2; }
        }
    }
    __syncthreads();
#pragma unroll
    for (int mi = 0; mi < 2; mi++) {
#pragma unroll
        for (int hh = 0; hh < 2; hh++) {
            int rl = wm * 32 + mi * 16 + gq + hh * 8;
            int r  = row0 + rl;
            float S1 = s_sum[rl][0] + s_sum[rl][1] + s_sum[rl][2] + s_sum[rl][3];
            float S2 = s_sq [rl][0] + s_sq [rl][1] + s_sq [rl][2] + s_sq [rl][3];
            float mean = S1 * (1.0f / 192.0f);
            float var  = S2 * (1.0f / 192.0f) - mean * mean;
            float rstd = rsqrtf(var + 1e-5f);
#pragma unroll
            for (int ni = 0; ni < 6; ni++) {
                int col = wn * 48 + ni * 8 + tg * 2;
                float v0 = acc[mi][ni][hh*2], v1 = acc[mi][ni][hh*2 + 1];
                *(float2*)(g_x2 + (size_t)r * 192 + col) = make_float2(v0, v1);
                float n0 = (v0 - mean) * rstd * gam[col]     + bet[col];
                float n1 = (v1 - mean) * rstd * gam[col + 1] + bet[col + 1];
                *(__nv_bfloat162*)(g_h + (size_t)r * 192 + col) =
                    __floats2bfloat162_rn(n0, n1);
            }
        }
    }
}

// ---------------- host launcher ----------------
extern "C" void kernel_launch(void* const* d_in, const int* in_sizes, int n_in,
                              void* d_out, int out_size)
{
    const float* x      = (const float*)d_in[0];
    const float* ln1_g  = (const float*)d_in[1];
    const float* ln1_b  = (const float*)d_in[2];
    const float* qkv_w  = (const float*)d_in[3];
    const float* qkv_b  = (const float*)d_in[4];
    const float* btab   = (const float*)d_in[5];
    const float* proj_w = (const float*)d_in[6];
    const float* proj_b = (const float*)d_in[7];
    const float* ln2_g  = (const float*)d_in[8];
    const float* ln2_b  = (const float*)d_in[9];
    const float* mlp_w1 = (const float*)d_in[10];
    const float* mlp_b1 = (const float*)d_in[11];
    const float* mlp_w2 = (const float*)d_in[12];
    const float* mlp_b2 = (const float*)d_in[13];
    const int*   rel_idx= (const int*)d_in[14];
    float*       out    = (float*)d_out;

    bf16 *p_h, *p_qkv, *p_attn, *p_hid;
    float *p_x2;
    bf16 *p_qkv_wt, *p_proj_wt, *p_w1t, *p_w2t;
    cudaGetSymbolAddress((void**)&p_h,    g_h);
    cudaGetSymbolAddress((void**)&p_qkv,  g_qkv);
    cudaGetSymbolAddress((void**)&p_attn, g_attn);
    cudaGetSymbolAddress((void**)&p_x2,   g_x2);
    cudaGetSymbolAddress((void**)&p_hid,  g_hid);
    cudaGetSymbolAddress((void**)&p_qkv_wt,  g_qkv_wt);
    cudaGetSymbolAddress((void**)&p_proj_wt, g_proj_wt);
    cudaGetSymbolAddress((void**)&p_w1t,  g_w1t);
    cudaGetSymbolAddress((void**)&p_w2t,  g_w2t);

    cudaFuncSetAttribute(tc_gemm<0>, cudaFuncAttributeMaxDynamicSharedMemorySize, GEMM_SMEM);
    cudaFuncSetAttribute(tc_gemm<1>, cudaFuncAttributeMaxDynamicSharedMemorySize, GEMM_SMEM);
    cudaFuncSetAttribute(tc_gemm<3>, cudaFuncAttributeMaxDynamicSharedMemorySize, GEMM_SMEM);
    cudaFuncSetAttribute(proj_ln2_kernel, cudaFuncAttributeMaxDynamicSharedMemorySize, PROJ_SMEM);

    prep_kernel<<<446 + NTOK_TOTAL / 8, 256>>>(qkv_w, proj_w, mlp_w1, mlp_w2,
                                               btab, rel_idx, x, ln1_g, ln1_b);

    const int Mb = NTOK_TOTAL / 128;  // 1008
    tc_gemm<0><<<dim3(6, Mb), 256, GEMM_SMEM>>>(p_h, p_qkv_wt, qkv_b, nullptr, p_qkv, 576, 192);
    attn_kernel<<<NWIN * HEADS / 8, 256>>>();
    proj_ln2_kernel<<<NTOK_TOTAL / 64, 256, PROJ_SMEM>>>(p_attn, p_proj_wt, proj_b, x, ln2_g, ln2_b);
    tc_gemm<1><<<dim3(8, Mb), 256, GEMM_SMEM>>>(p_h, p_w1t, mlp_b1, nullptr, p_hid, 768, 192);
    tc_gemm<3><<<dim3(2, Mb), 256, GEMM_SMEM>>>(p_hid, p_w2t, mlp_b2, p_x2, out, 192, 768);
}